// round 16
// baseline (speedup 1.0000x reference)
#include <cuda_runtime.h>
#include <cstdint>

#define N_NODES 50000
#define X_DIMS 256
#define Y_DIMS 64

// ---------------- scratch (no cudaMalloc allowed) ----------------
__device__ int   g_row_ptr[N_NODES + 1];
__device__ float g_x1[(size_t)N_NODES * X_DIMS];
__device__ float g_x2[(size_t)N_NODES * X_DIMS];
__device__ float g_y1[(size_t)N_NODES * Y_DIMS];
__device__ float g_y2[(size_t)N_NODES * Y_DIMS];
__device__ float g_wr[X_DIMS * 3 * 64 + Y_DIMS * 2 * 64]; // tf32-rounded W [896*64]
__device__ float g_sqn_x [N_NODES];
__device__ float g_sqn_x1[N_NODES];
__device__ float g_sqn_y1[N_NODES];

// ---------------- tf32 helpers ----------------
__device__ __forceinline__ float tf32r(float f)
{
    uint32_t u;
    asm("cvt.rna.tf32.f32 %0, %1;" : "=r"(u) : "f"(f));
    return __uint_as_float(u);
}
__device__ __forceinline__ uint32_t f2tf32(float f)
{
    uint32_t u;
    asm("cvt.rna.tf32.f32 %0, %1;" : "=r"(u) : "f"(f));
    return u;
}

// ---------------- cp.async helpers ----------------
__device__ __forceinline__ void cpa16(uint32_t dst, const float* src, int sz)
{
    asm volatile("cp.async.cg.shared.global [%0], [%1], 16, %2;"
                 :: "r"(dst), "l"(src), "r"(sz));
}
__device__ __forceinline__ void cpa_commit()
{
    asm volatile("cp.async.commit_group;");
}
template <int N>
__device__ __forceinline__ void cpa_wait()
{
    asm volatile("cp.async.wait_group %0;" :: "n"(N));
}

// ---------------- CSR row_ptr from sorted COO row ----------------
__global__ void build_rowptr_kernel(const int* __restrict__ row, int E, int n)
{
    int r = blockIdx.x * blockDim.x + threadIdx.x;
    if (r > n) return;
    int lo = 0, hi = E;
    while (lo < hi) {
        int mid = (lo + hi) >> 1;
        if (row[mid] < r) lo = mid + 1; else hi = mid;
    }
    g_row_ptr[r] = lo;
}

// ---------------- tf32 rounding copy kernel (W only: tiny) ----------------
__global__ void __launch_bounds__(256) round_kernel(
    const float* __restrict__ in, float* __restrict__ out, int n4)
{
    int i = blockIdx.x * blockDim.x + threadIdx.x;
    if (i >= n4) return;
    float4 v = ((const float4*)in)[i];
    v.x = tf32r(v.x); v.y = tf32r(v.y); v.z = tf32r(v.z); v.w = tf32r(v.w);
    ((float4*)out)[i] = v;
}

// ---------------- row load helpers ----------------
__device__ __forceinline__ void load_row(const float* __restrict__ p, int lane, float (&v)[8])
{
    float4 a = *(const float4*)(p + lane * 4);
    float4 b = *(const float4*)(p + 128 + lane * 4);
    v[0]=a.x; v[1]=a.y; v[2]=a.z; v[3]=a.w;
    v[4]=b.x; v[5]=b.y; v[6]=b.z; v[7]=b.w;
}
__device__ __forceinline__ void load_row(const float* __restrict__ p, int lane, float (&v)[2])
{
    float2 a = *(const float2*)(p + lane * 2);
    v[0]=a.x; v[1]=a.y;
}

// ---------------- squared-norm kernel (warp per row; x only) ---------------
template <int D>
__global__ void __launch_bounds__(256) norm_kernel(
    const float* __restrict__ feats, float* __restrict__ sqn, int n)
{
    constexpr int C = D / 32;
    int gw   = (int)((blockIdx.x * 256u + threadIdx.x) >> 5);
    int lane = threadIdx.x & 31;
    if (gw >= n) return;
    float fr[C];
    load_row(feats + (size_t)gw * D, lane, fr);
    float s = 0.0f;
#pragma unroll
    for (int i = 0; i < C; i++) s = fmaf(fr[i], fr[i], s);
#pragma unroll
    for (int o = 16; o > 0; o >>= 1)
        s += __shfl_xor_sync(0xffffffffu, s, o);
    if (lane == 0) sqn[gw] = s;
}

// ---------------- prop: warp per row, U edges in flight (R11 shape) --------
// ||fr-fc||^2 = nr + nc - 2 dot(fr,fc); per-node sq-norms precomputed.
// ONES: all source sq-norms are exactly 1.0 (y_one_hot) -> no norm loads.
// Output rows stored tf32-RNA-rounded; sq-norm computed from rounded values.
template <int D, int U, bool WN, bool ONES>
__global__ void __launch_bounds__(256) prop_kernel(
    const float* __restrict__ feats,
    const int*   __restrict__ col,
    const float* __restrict__ sqn_src,
    float*       __restrict__ sqn_dst,
    const float* __restrict__ sigmas, int sidx,
    float* __restrict__ out, int n)
{
    constexpr int C = D / 32;
    int gw   = (int)((blockIdx.x * 256u + threadIdx.x) >> 5);
    int lane = threadIdx.x & 31;
    if (gw >= n) return;

    float sg = sigmas[sidx];
    float inv_s2 = 1.0f / (sg * sg);
    float t2 = 2.0f * inv_s2;

    int e0 = g_row_ptr[gw];
    int e1 = g_row_ptr[gw + 1];

    float fr[C], acc[C];
    load_row(feats + (size_t)gw * D, lane, fr);
    float bnr = ONES ? -inv_s2 : -sqn_src[gw] * inv_s2;
#pragma unroll
    for (int i = 0; i < C; i++) acc[i] = 0.0f;
    float den = 0.0f;

    int e = e0;
    for (; e + U <= e1; e += U) {
        int cs[U];
        float nc[U];
#pragma unroll
        for (int j = 0; j < U; j++) {
            cs[j] = __ldg(col + e + j);
            nc[j] = ONES ? 1.0f : __ldg(sqn_src + cs[j]);
        }
        float fc[U][C];
#pragma unroll
        for (int j = 0; j < U; j++)
            load_row(feats + (size_t)cs[j] * D, lane, fc[j]);

        float dt[U];
#pragma unroll
        for (int j = 0; j < U; j++) {
            float d = 0.0f;
#pragma unroll
            for (int i = 0; i < C; i++) d = fmaf(fr[i], fc[j][i], d);
            dt[j] = d;
        }
#pragma unroll
        for (int o = 16; o > 0; o >>= 1) {
#pragma unroll
            for (int j = 0; j < U; j++)
                dt[j] += __shfl_xor_sync(0xffffffffu, dt[j], o);
        }
#pragma unroll
        for (int j = 0; j < U; j++) {
            float val = __expf(fmaf(t2, dt[j], fmaf(-inv_s2, nc[j], bnr)));
            den += val;
#pragma unroll
            for (int i = 0; i < C; i++) acc[i] = fmaf(val, fc[j][i], acc[i]);
        }
    }
    for (; e < e1; e++) {
        int c = __ldg(col + e);
        float ncv = ONES ? 1.0f : __ldg(sqn_src + c);
        float fc[C];
        load_row(feats + (size_t)c * D, lane, fc);
        float d = 0.0f;
#pragma unroll
        for (int i = 0; i < C; i++) d = fmaf(fr[i], fc[i], d);
#pragma unroll
        for (int o = 16; o > 0; o >>= 1)
            d += __shfl_xor_sync(0xffffffffu, d, o);
        float val = __expf(fmaf(t2, d, fmaf(-inv_s2, ncv, bnr)));
        den += val;
#pragma unroll
        for (int i = 0; i < C; i++) acc[i] = fmaf(val, fc[i], acc[i]);
    }

    float inv = (den > 0.0f) ? (1.0f / den) : 0.0f;
#pragma unroll
    for (int i = 0; i < C; i++) acc[i] = tf32r(acc[i] * inv);

    float* op = out + (size_t)gw * D;
    if (C == 8) {
        *(float4*)(op + lane * 4)       = make_float4(acc[0], acc[1], acc[2], acc[3]);
        *(float4*)(op + 128 + lane * 4) = make_float4(acc[4], acc[5], acc[6], acc[7]);
    } else {
        *(float2*)(op + lane * 2) = make_float2(acc[0], acc[1]);
    }

    if (WN) {
        float s = 0.0f;
#pragma unroll
        for (int i = 0; i < C; i++) s = fmaf(acc[i], acc[i], s);
#pragma unroll
        for (int o = 16; o > 0; o >>= 1)
            s += __shfl_xor_sync(0xffffffffu, s, o);
        if (lane == 0) sqn_dst[gw] = s;
    }
}

// ---------------- tf32 GEMM v3b (R11 measured-best): cp.async 4-stage ------
#define BM 128
#define BN 64
#define BK 32
#define AP (BK + 4)
#define BP (BN + 8)
#define NT 28
#define NSTG 4
#define SMEM_GEMM (NSTG * (BM * AP + BK * BP) * 4)

__device__ __forceinline__ void mma_tf32(float (&c)[4], const uint32_t (&a)[4], const uint32_t (&b)[2])
{
    asm volatile(
        "mma.sync.aligned.m16n8k8.row.col.f32.tf32.tf32.f32 "
        "{%0,%1,%2,%3}, {%4,%5,%6,%7}, {%8,%9}, {%0,%1,%2,%3};\n"
        : "+f"(c[0]), "+f"(c[1]), "+f"(c[2]), "+f"(c[3])
        : "r"(a[0]), "r"(a[1]), "r"(a[2]), "r"(a[3]), "r"(b[0]), "r"(b[1]));
}

__device__ __forceinline__ const float* tile_base(
    int t, const float* x, const float* x1, const float* x2,
    const float* y1, const float* y2, int& width)
{
    if (t < 8)  { width = X_DIMS; return x  + (t << 5); }
    if (t < 16) { width = X_DIMS; return x1 + ((t - 8) << 5); }
    if (t < 24) { width = X_DIMS; return x2 + ((t - 16) << 5); }
    if (t < 26) { width = Y_DIMS; return y1 + ((t - 24) << 5); }
    width = Y_DIMS; return y2 + ((t - 26) << 5);
}

__global__ void __launch_bounds__(256) gemm_tf32_kernel(
    const float* __restrict__ x,
    const float* __restrict__ x1,
    const float* __restrict__ x2,
    const float* __restrict__ y1,
    const float* __restrict__ y2,
    const float* __restrict__ W,
    float* __restrict__ out, int M)
{
    extern __shared__ float dsm[];
    float (*As)[BM][AP] = (float (*)[BM][AP])dsm;
    float (*Bs)[BK][BP] = (float (*)[BK][BP])(dsm + NSTG * BM * AP);

    uint32_t smA = (uint32_t)__cvta_generic_to_shared(dsm);
    uint32_t smB = smA + NSTG * BM * AP * 4;

    int tid  = threadIdx.x;
    int lane = tid & 31;
    int wid  = tid >> 5;
    int wm = (wid >> 1) * 32;
    int wn = (wid & 1) * 32;
    int g  = lane >> 2;
    int tk = lane & 3;
    int row0 = blockIdx.x * BM;

    int ar = tid >> 3;
    int kg = (tid & 7) * 4;
    int bk_ = tid >> 4;
    int bj  = (tid & 15) * 4;

    float c[2][4][4];
#pragma unroll
    for (int mt = 0; mt < 2; mt++)
#pragma unroll
        for (int nt = 0; nt < 4; nt++)
#pragma unroll
            for (int q = 0; q < 4; q++) c[mt][nt][q] = 0.0f;

#define LDG_ASYNC(t, s)                                                     \
    do {                                                                    \
        int width_;                                                         \
        const float* base_ = tile_base((t), x, x1, x2, y1, y2, width_);     \
        _Pragma("unroll")                                                   \
        for (int i = 0; i < 4; i++) {                                       \
            int grow = row0 + ar + 32 * i;                                  \
            const float* src = base_ + (size_t)min(grow, M - 1) * width_ + kg;\
            int sz = (grow < M) ? 16 : 0;                                   \
            cpa16(smA + (uint32_t)(((s) * BM + ar + 32 * i) * AP + kg) * 4, \
                  src, sz);                                                 \
        }                                                                   \
        _Pragma("unroll")                                                   \
        for (int i = 0; i < 2; i++) {                                       \
            int k_ = bk_ + 16 * i;                                          \
            cpa16(smB + (uint32_t)(((s) * BK + k_) * BP + bj) * 4,          \
                  W + (size_t)((t) * BK + k_) * BN + bj, 16);               \
        }                                                                   \
    } while (0)

    // prologue: 3 tiles in flight
#pragma unroll
    for (int s = 0; s < 3; s++) {
        LDG_ASYNC(s, s);
        cpa_commit();
    }

    for (int t = 0; t < NT; t++) {
        cpa_wait<2>();
        __syncthreads();

        int buf = t & (NSTG - 1);
        bool cvt_a = (t < 8);
#pragma unroll
        for (int kk = 0; kk < BK; kk += 8) {
            uint32_t a[2][4];
#pragma unroll
            for (int mt = 0; mt < 2; mt++) {
                int mrow = wm + mt * 16 + g;
                a[mt][0] = __float_as_uint(As[buf][mrow][kk + tk]);
                a[mt][1] = __float_as_uint(As[buf][mrow + 8][kk + tk]);
                a[mt][2] = __float_as_uint(As[buf][mrow][kk + tk + 4]);
                a[mt][3] = __float_as_uint(As[buf][mrow + 8][kk + tk + 4]);
            }
            if (cvt_a) {
#pragma unroll
                for (int mt = 0; mt < 2; mt++)
#pragma unroll
                    for (int q = 0; q < 4; q++)
                        a[mt][q] = f2tf32(__uint_as_float(a[mt][q]));
            }
            uint32_t b[4][2];
#pragma unroll
            for (int nt = 0; nt < 4; nt++) {
                int ncol = wn + nt * 8 + g;
                b[nt][0] = __float_as_uint(Bs[buf][kk + tk][ncol]);
                b[nt][1] = __float_as_uint(Bs[buf][kk + tk + 4][ncol]);
            }
#pragma unroll
            for (int mt = 0; mt < 2; mt++)
#pragma unroll
                for (int nt = 0; nt < 4; nt++)
                    mma_tf32(c[mt][nt], a[mt], b[nt]);
        }

        if (t + 3 < NT)
            LDG_ASYNC(t + 3, (t + 3) & (NSTG - 1));
        cpa_commit();
    }

#pragma unroll
    for (int mt = 0; mt < 2; mt++) {
#pragma unroll
        for (int nt = 0; nt < 4; nt++) {
            int r0 = row0 + wm + mt * 16 + g;
            int cc = wn + nt * 8 + 2 * tk;
            if (r0 < M)
                *(float2*)(out + (size_t)r0 * BN + cc) = make_float2(c[mt][nt][0], c[mt][nt][1]);
            if (r0 + 8 < M)
                *(float2*)(out + (size_t)(r0 + 8) * BN + cc) = make_float2(c[mt][nt][2], c[mt][nt][3]);
        }
    }
}

// ---------------- launch ----------------
extern "C" void kernel_launch(void* const* d_in, const int* in_sizes, int n_in,
                              void* d_out, int out_size)
{
    const float* x   = (const float*)d_in[0];
    const float* y   = (const float*)d_in[1];
    const float* W   = (const float*)d_in[2];
    const float* sig = (const float*)d_in[3];
    const int*   row = (const int*)  d_in[4];
    const int*   col = (const int*)  d_in[5];

    int N = in_sizes[0] / X_DIMS;
    int E = in_sizes[4];
    int Wn = in_sizes[2];

    float *px1, *px2, *py1, *py2, *pwr, *nx, *nx1, *ny1;
    cudaGetSymbolAddress((void**)&px1, g_x1);
    cudaGetSymbolAddress((void**)&px2, g_x2);
    cudaGetSymbolAddress((void**)&py1, g_y1);
    cudaGetSymbolAddress((void**)&py2, g_y2);
    cudaGetSymbolAddress((void**)&pwr, g_wr);
    cudaGetSymbolAddress((void**)&nx,  g_sqn_x);
    cudaGetSymbolAddress((void**)&nx1, g_sqn_x1);
    cudaGetSymbolAddress((void**)&ny1, g_sqn_y1);

    cudaFuncSetAttribute(gemm_tf32_kernel,
                         cudaFuncAttributeMaxDynamicSharedMemorySize, SMEM_GEMM);

    build_rowptr_kernel<<<(N + 1 + 255) / 256, 256>>>(row, E, N);

    int w4 = Wn / 4;
    round_kernel<<<(w4 + 255) / 256, 256>>>(W, pwr, w4);

    int pb = (N * 32 + 255) / 256;   // one warp per row
    norm_kernel<X_DIMS><<<pb, 256>>>(x, nx, N);

    // Y props now run U=8 (double the gather chains; C=2 keeps regs ~50)
    prop_kernel<X_DIMS, 2, true,  false><<<pb, 256>>>(x,   col, nx,  nx1, sig, 0, px1, N);
    prop_kernel<Y_DIMS, 8, true,  true ><<<pb, 256>>>(y,   col, nullptr, ny1, sig, 2, py1, N);
    prop_kernel<X_DIMS, 2, false, false><<<pb, 256>>>(px1, col, nx1, nullptr, sig, 1, px2, N);
    prop_kernel<Y_DIMS, 8, false, false><<<pb, 256>>>(py1, col, ny1, nullptr, sig, 3, py2, N);

    gemm_tf32_kernel<<<(N + BM - 1) / BM, 256, SMEM_GEMM>>>(
        x, px1, px2, py1, py2, pwr, (float*)d_out, N);
}

// round 17
// speedup vs baseline: 1.0249x; 1.0249x over previous
#include <cuda_runtime.h>
#include <cstdint>

#define N_NODES 50000
#define X_DIMS 256
#define Y_DIMS 64
#define LOG2E 1.4426950408889634f

// ---------------- scratch (no cudaMalloc allowed) ----------------
__device__ int   g_row_ptr[N_NODES + 1];
__device__ float g_x1[(size_t)N_NODES * X_DIMS];
__device__ float g_x2[(size_t)N_NODES * X_DIMS];
__device__ float g_y1[(size_t)N_NODES * Y_DIMS];
__device__ float g_y2[(size_t)N_NODES * Y_DIMS];
__device__ float g_wr[X_DIMS * 3 * 64 + Y_DIMS * 2 * 64]; // tf32-rounded W [896*64]
__device__ float g_sqn_x [N_NODES];
__device__ float g_sqn_x1[N_NODES];
__device__ float g_sqn_y1[N_NODES];

// ---------------- tf32 helpers ----------------
__device__ __forceinline__ float tf32r(float f)
{
    uint32_t u;
    asm("cvt.rna.tf32.f32 %0, %1;" : "=r"(u) : "f"(f));
    return __uint_as_float(u);
}
__device__ __forceinline__ uint32_t f2tf32(float f)
{
    uint32_t u;
    asm("cvt.rna.tf32.f32 %0, %1;" : "=r"(u) : "f"(f));
    return u;
}

// ---------------- cp.async helpers ----------------
__device__ __forceinline__ void cpa16(uint32_t dst, const float* src, int sz)
{
    asm volatile("cp.async.cg.shared.global [%0], [%1], 16, %2;"
                 :: "r"(dst), "l"(src), "r"(sz));
}
__device__ __forceinline__ void cpa_commit()
{
    asm volatile("cp.async.commit_group;");
}
template <int N>
__device__ __forceinline__ void cpa_wait()
{
    asm volatile("cp.async.wait_group %0;" :: "n"(N));
}

// ---------------- CSR row_ptr from sorted COO row ----------------
__global__ void build_rowptr_kernel(const int* __restrict__ row, int E, int n)
{
    int r = blockIdx.x * blockDim.x + threadIdx.x;
    if (r > n) return;
    int lo = 0, hi = E;
    while (lo < hi) {
        int mid = (lo + hi) >> 1;
        if (row[mid] < r) lo = mid + 1; else hi = mid;
    }
    g_row_ptr[r] = lo;
}

// ---------------- tf32 rounding copy kernel (W only: tiny) ----------------
__global__ void __launch_bounds__(256) round_kernel(
    const float* __restrict__ in, float* __restrict__ out, int n4)
{
    int i = blockIdx.x * blockDim.x + threadIdx.x;
    if (i >= n4) return;
    float4 v = ((const float4*)in)[i];
    v.x = tf32r(v.x); v.y = tf32r(v.y); v.z = tf32r(v.z); v.w = tf32r(v.w);
    ((float4*)out)[i] = v;
}

// ---------------- row load helpers ----------------
__device__ __forceinline__ void load_row(const float* __restrict__ p, int lane, float (&v)[8])
{
    float4 a = *(const float4*)(p + lane * 4);
    float4 b = *(const float4*)(p + 128 + lane * 4);
    v[0]=a.x; v[1]=a.y; v[2]=a.z; v[3]=a.w;
    v[4]=b.x; v[5]=b.y; v[6]=b.z; v[7]=b.w;
}
__device__ __forceinline__ void load_row(const float* __restrict__ p, int lane, float (&v)[2])
{
    float2 a = *(const float2*)(p + lane * 2);
    v[0]=a.x; v[1]=a.y;
}

// ---------------- squared-norm kernel (warp per row; x only) ---------------
template <int D>
__global__ void __launch_bounds__(256) norm_kernel(
    const float* __restrict__ feats, float* __restrict__ sqn, int n)
{
    constexpr int C = D / 32;
    int gw   = (int)((blockIdx.x * 256u + threadIdx.x) >> 5);
    int lane = threadIdx.x & 31;
    if (gw >= n) return;
    float fr[C];
    load_row(feats + (size_t)gw * D, lane, fr);
    float s = 0.0f;
#pragma unroll
    for (int i = 0; i < C; i++) s = fmaf(fr[i], fr[i], s);
#pragma unroll
    for (int o = 16; o > 0; o >>= 1)
        s += __shfl_xor_sync(0xffffffffu, s, o);
    if (lane == 0) sqn[gw] = s;
}

// ---------------- prop: warp per row, U edges in flight (R11 shape) --------
// ||fr-fc||^2 = nr + nc - 2 dot(fr,fc); per-node sq-norms precomputed.
// ONES: all source sq-norms are exactly 1.0 (y_one_hot) -> no norm loads.
// exp via exp2f with log2e pre-folded into the constants (1 fewer FMA/edge).
// Output rows stored tf32-RNA-rounded; sq-norm computed from rounded values.
template <int D, int U, bool WN, bool ONES>
__global__ void __launch_bounds__(256) prop_kernel(
    const float* __restrict__ feats,
    const int*   __restrict__ col,
    const float* __restrict__ sqn_src,
    float*       __restrict__ sqn_dst,
    const float* __restrict__ sigmas, int sidx,
    float* __restrict__ out, int n)
{
    constexpr int C = D / 32;
    int gw   = (int)((blockIdx.x * 256u + threadIdx.x) >> 5);
    int lane = threadIdx.x & 31;
    if (gw >= n) return;

    float sg = sigmas[sidx];
    float inv_s2  = 1.0f / (sg * sg);
    float inv_s2l = inv_s2 * LOG2E;      // log2e-folded constants
    float t2l     = 2.0f * inv_s2l;

    int e0 = g_row_ptr[gw];
    int e1 = g_row_ptr[gw + 1];

    float fr[C], acc[C];
    load_row(feats + (size_t)gw * D, lane, fr);
    float bnrl = ONES ? -inv_s2l : -sqn_src[gw] * inv_s2l;
#pragma unroll
    for (int i = 0; i < C; i++) acc[i] = 0.0f;
    float den = 0.0f;

    int e = e0;
    for (; e + U <= e1; e += U) {
        int cs[U];
        float nc[U];
#pragma unroll
        for (int j = 0; j < U; j++) {
            cs[j] = __ldg(col + e + j);
            nc[j] = ONES ? 1.0f : __ldg(sqn_src + cs[j]);
        }
        float fc[U][C];
#pragma unroll
        for (int j = 0; j < U; j++)
            load_row(feats + (size_t)cs[j] * D, lane, fc[j]);

        float dt[U];
#pragma unroll
        for (int j = 0; j < U; j++) {
            float d = 0.0f;
#pragma unroll
            for (int i = 0; i < C; i++) d = fmaf(fr[i], fc[j][i], d);
            dt[j] = d;
        }
#pragma unroll
        for (int o = 16; o > 0; o >>= 1) {
#pragma unroll
            for (int j = 0; j < U; j++)
                dt[j] += __shfl_xor_sync(0xffffffffu, dt[j], o);
        }
#pragma unroll
        for (int j = 0; j < U; j++) {
            float val = exp2f(fmaf(t2l, dt[j], fmaf(-inv_s2l, nc[j], bnrl)));
            den += val;
#pragma unroll
            for (int i = 0; i < C; i++) acc[i] = fmaf(val, fc[j][i], acc[i]);
        }
    }
    for (; e < e1; e++) {
        int c = __ldg(col + e);
        float ncv = ONES ? 1.0f : __ldg(sqn_src + c);
        float fc[C];
        load_row(feats + (size_t)c * D, lane, fc);
        float d = 0.0f;
#pragma unroll
        for (int i = 0; i < C; i++) d = fmaf(fr[i], fc[i], d);
#pragma unroll
        for (int o = 16; o > 0; o >>= 1)
            d += __shfl_xor_sync(0xffffffffu, d, o);
        float val = exp2f(fmaf(t2l, d, fmaf(-inv_s2l, ncv, bnrl)));
        den += val;
#pragma unroll
        for (int i = 0; i < C; i++) acc[i] = fmaf(val, fc[i], acc[i]);
    }

    float inv = (den > 0.0f) ? (1.0f / den) : 0.0f;
#pragma unroll
    for (int i = 0; i < C; i++) acc[i] = tf32r(acc[i] * inv);

    float* op = out + (size_t)gw * D;
    if (C == 8) {
        *(float4*)(op + lane * 4)       = make_float4(acc[0], acc[1], acc[2], acc[3]);
        *(float4*)(op + 128 + lane * 4) = make_float4(acc[4], acc[5], acc[6], acc[7]);
    } else {
        *(float2*)(op + lane * 2) = make_float2(acc[0], acc[1]);
    }

    if (WN) {
        float s = 0.0f;
#pragma unroll
        for (int i = 0; i < C; i++) s = fmaf(acc[i], acc[i], s);
#pragma unroll
        for (int o = 16; o > 0; o >>= 1)
            s += __shfl_xor_sync(0xffffffffu, s, o);
        if (lane == 0) sqn_dst[gw] = s;
    }
}

// ---------------- tf32 GEMM v3b (R11 measured-best): cp.async 4-stage ------
#define BM 128
#define BN 64
#define BK 32
#define AP (BK + 4)
#define BP (BN + 8)
#define NT 28
#define NSTG 4
#define SMEM_GEMM (NSTG * (BM * AP + BK * BP) * 4)

__device__ __forceinline__ void mma_tf32(float (&c)[4], const uint32_t (&a)[4], const uint32_t (&b)[2])
{
    asm volatile(
        "mma.sync.aligned.m16n8k8.row.col.f32.tf32.tf32.f32 "
        "{%0,%1,%2,%3}, {%4,%5,%6,%7}, {%8,%9}, {%0,%1,%2,%3};\n"
        : "+f"(c[0]), "+f"(c[1]), "+f"(c[2]), "+f"(c[3])
        : "r"(a[0]), "r"(a[1]), "r"(a[2]), "r"(a[3]), "r"(b[0]), "r"(b[1]));
}

__device__ __forceinline__ const float* tile_base(
    int t, const float* x, const float* x1, const float* x2,
    const float* y1, const float* y2, int& width)
{
    if (t < 8)  { width = X_DIMS; return x  + (t << 5); }
    if (t < 16) { width = X_DIMS; return x1 + ((t - 8) << 5); }
    if (t < 24) { width = X_DIMS; return x2 + ((t - 16) << 5); }
    if (t < 26) { width = Y_DIMS; return y1 + ((t - 24) << 5); }
    width = Y_DIMS; return y2 + ((t - 26) << 5);
}

__global__ void __launch_bounds__(256) gemm_tf32_kernel(
    const float* __restrict__ x,
    const float* __restrict__ x1,
    const float* __restrict__ x2,
    const float* __restrict__ y1,
    const float* __restrict__ y2,
    const float* __restrict__ W,
    float* __restrict__ out, int M)
{
    extern __shared__ float dsm[];
    float (*As)[BM][AP] = (float (*)[BM][AP])dsm;
    float (*Bs)[BK][BP] = (float (*)[BK][BP])(dsm + NSTG * BM * AP);

    uint32_t smA = (uint32_t)__cvta_generic_to_shared(dsm);
    uint32_t smB = smA + NSTG * BM * AP * 4;

    int tid  = threadIdx.x;
    int lane = tid & 31;
    int wid  = tid >> 5;
    int wm = (wid >> 1) * 32;
    int wn = (wid & 1) * 32;
    int g  = lane >> 2;
    int tk = lane & 3;
    int row0 = blockIdx.x * BM;

    int ar = tid >> 3;
    int kg = (tid & 7) * 4;
    int bk_ = tid >> 4;
    int bj  = (tid & 15) * 4;

    float c[2][4][4];
#pragma unroll
    for (int mt = 0; mt < 2; mt++)
#pragma unroll
        for (int nt = 0; nt < 4; nt++)
#pragma unroll
            for (int q = 0; q < 4; q++) c[mt][nt][q] = 0.0f;

#define LDG_ASYNC(t, s)                                                     \
    do {                                                                    \
        int width_;                                                         \
        const float* base_ = tile_base((t), x, x1, x2, y1, y2, width_);     \
        _Pragma("unroll")                                                   \
        for (int i = 0; i < 4; i++) {                                       \
            int grow = row0 + ar + 32 * i;                                  \
            const float* src = base_ + (size_t)min(grow, M - 1) * width_ + kg;\
            int sz = (grow < M) ? 16 : 0;                                   \
            cpa16(smA + (uint32_t)(((s) * BM + ar + 32 * i) * AP + kg) * 4, \
                  src, sz);                                                 \
        }                                                                   \
        _Pragma("unroll")                                                   \
        for (int i = 0; i < 2; i++) {                                       \
            int k_ = bk_ + 16 * i;                                          \
            cpa16(smB + (uint32_t)(((s) * BK + k_) * BP + bj) * 4,          \
                  W + (size_t)((t) * BK + k_) * BN + bj, 16);               \
        }                                                                   \
    } while (0)

    // prologue: 3 tiles in flight
#pragma unroll
    for (int s = 0; s < 3; s++) {
        LDG_ASYNC(s, s);
        cpa_commit();
    }

    for (int t = 0; t < NT; t++) {
        cpa_wait<2>();
        __syncthreads();

        int buf = t & (NSTG - 1);
        bool cvt_a = (t < 8);
#pragma unroll
        for (int kk = 0; kk < BK; kk += 8) {
            uint32_t a[2][4];
#pragma unroll
            for (int mt = 0; mt < 2; mt++) {
                int mrow = wm + mt * 16 + g;
                a[mt][0] = __float_as_uint(As[buf][mrow][kk + tk]);
                a[mt][1] = __float_as_uint(As[buf][mrow + 8][kk + tk]);
                a[mt][2] = __float_as_uint(As[buf][mrow][kk + tk + 4]);
                a[mt][3] = __float_as_uint(As[buf][mrow + 8][kk + tk + 4]);
            }
            if (cvt_a) {
#pragma unroll
                for (int mt = 0; mt < 2; mt++)
#pragma unroll
                    for (int q = 0; q < 4; q++)
                        a[mt][q] = f2tf32(__uint_as_float(a[mt][q]));
            }
            uint32_t b[4][2];
#pragma unroll
            for (int nt = 0; nt < 4; nt++) {
                int ncol = wn + nt * 8 + g;
                b[nt][0] = __float_as_uint(Bs[buf][kk + tk][ncol]);
                b[nt][1] = __float_as_uint(Bs[buf][kk + tk + 4][ncol]);
            }
#pragma unroll
            for (int mt = 0; mt < 2; mt++)
#pragma unroll
                for (int nt = 0; nt < 4; nt++)
                    mma_tf32(c[mt][nt], a[mt], b[nt]);
        }

        if (t + 3 < NT)
            LDG_ASYNC(t + 3, (t + 3) & (NSTG - 1));
        cpa_commit();
    }

#pragma unroll
    for (int mt = 0; mt < 2; mt++) {
#pragma unroll
        for (int nt = 0; nt < 4; nt++) {
            int r0 = row0 + wm + mt * 16 + g;
            int cc = wn + nt * 8 + 2 * tk;
            if (r0 < M)
                *(float2*)(out + (size_t)r0 * BN + cc) = make_float2(c[mt][nt][0], c[mt][nt][1]);
            if (r0 + 8 < M)
                *(float2*)(out + (size_t)(r0 + 8) * BN + cc) = make_float2(c[mt][nt][2], c[mt][nt][3]);
        }
    }
}

// ---------------- launch ----------------
extern "C" void kernel_launch(void* const* d_in, const int* in_sizes, int n_in,
                              void* d_out, int out_size)
{
    const float* x   = (const float*)d_in[0];
    const float* y   = (const float*)d_in[1];
    const float* W   = (const float*)d_in[2];
    const float* sig = (const float*)d_in[3];
    const int*   row = (const int*)  d_in[4];
    const int*   col = (const int*)  d_in[5];

    int N = in_sizes[0] / X_DIMS;
    int E = in_sizes[4];
    int Wn = in_sizes[2];

    float *px1, *px2, *py1, *py2, *pwr, *nx, *nx1, *ny1;
    cudaGetSymbolAddress((void**)&px1, g_x1);
    cudaGetSymbolAddress((void**)&px2, g_x2);
    cudaGetSymbolAddress((void**)&py1, g_y1);
    cudaGetSymbolAddress((void**)&py2, g_y2);
    cudaGetSymbolAddress((void**)&pwr, g_wr);
    cudaGetSymbolAddress((void**)&nx,  g_sqn_x);
    cudaGetSymbolAddress((void**)&nx1, g_sqn_x1);
    cudaGetSymbolAddress((void**)&ny1, g_sqn_y1);

    cudaFuncSetAttribute(gemm_tf32_kernel,
                         cudaFuncAttributeMaxDynamicSharedMemorySize, SMEM_GEMM);

    build_rowptr_kernel<<<(N + 1 + 255) / 256, 256>>>(row, E, N);

    int w4 = Wn / 4;
    round_kernel<<<(w4 + 255) / 256, 256>>>(W, pwr, w4);

    int pb = (N * 32 + 255) / 256;   // one warp per row
    norm_kernel<X_DIMS><<<pb, 256>>>(x, nx, N);

    prop_kernel<X_DIMS, 2, true,  false><<<pb, 256>>>(x,   col, nx,  nx1, sig, 0, px1, N);
    prop_kernel<Y_DIMS, 4, true,  true ><<<pb, 256>>>(y,   col, nullptr, ny1, sig, 2, py1, N);
    prop_kernel<X_DIMS, 2, false, false><<<pb, 256>>>(px1, col, nx1, nullptr, sig, 1, px2, N);
    prop_kernel<Y_DIMS, 4, false, false><<<pb, 256>>>(py1, col, ny1, nullptr, sig, 3, py2, N);

    gemm_tf32_kernel<<<(N + BM - 1) / BM, 256, SMEM_GEMM>>>(
        x, px1, px2, py1, py2, pwr, (float*)d_out, N);
}